// round 13
// baseline (speedup 1.0000x reference)
#include <cuda_runtime.h>
#include <cuda_fp16.h>
#include <math.h>
#include <stdint.h>

#define BN 8
#define CC 128
#define HH 56
#define WW 56
#define HWSZ (HH*WW)

// ---------------- scratch ----------------
__device__ __align__(16) float g_h1[BN*CC*HWSZ];
__device__ __align__(16) float g_off[BN*18*HWSZ];
__device__ __align__(16) float g_offp[8*BN*18*HWSZ];
__device__ __align__(16) float g_h2[BN*CC*HWSZ];
__device__ __align__(16) float g_h3[BN*CC*HWSZ];
__device__ __align__(16) float g_maskp[4*BN*HWSZ];
__device__ __align__(16) float g_bnp[392*256];     // per-block BN partials [blk][s(128)|s2(128)]
__device__ float g_mean[CC];
__device__ float g_rstd[CC];
__device__ __align__(16) uint8_t g_w1g[144*8192];
__device__ __align__(16) uint8_t g_w2g[72*8192];
__device__ __align__(16) uint8_t g_wdg[72*8192];
__device__ __align__(16) float g_offwt[CC*18*12];
__device__ __align__(16) float g_maskwt[CC*12];

__device__ __forceinline__ uint32_t smem_u32(const void* p) {
    uint32_t a;
    asm("{ .reg .u64 t; cvta.to.shared.u64 t, %1; cvt.u32.u64 %0, t; }" : "=r"(a) : "l"(p));
    return a;
}
__device__ __forceinline__ uint16_t f16_bits(float x) {
    return __half_as_ushort(__float2half_rn(x));
}
__device__ __forceinline__ float f16_val(uint16_t u) {
    return __half2float(__ushort_as_half(u));
}

// ---------------- fused GEMM (fp16: A hi/lo pre-split, B single), K=64 per stage ----------------
// MODE 0: conv over concat(srcA,srcB)  (CIN=256)
// MODE 1: conv over srcA               (CIN=128)
// MODE 2: dcn - bilinear gather from g_h1 via g_off (CIN=128)
// BNS 1: emit per-block BN partial sums (conv2 only)
template<int CIN, int MODE, int BNS>
__global__ __launch_bounds__(256, 2) void gemm_fused(
    const float* __restrict__ srcA, const float* __restrict__ srcB,
    const uint8_t* __restrict__ Ag,
    const float* __restrict__ bias, float* __restrict__ out)
{
    constexpr int NST = CIN * 9 / 64;        // conv1: 36, others: 18
    __shared__ uint16_t sB[2][64][72];       // [buf][k][px]
    __shared__ float sSum[2][128][2];        // BN partials (BNS only)
    const int tid = threadIdx.x, lid = tid & 31, wid = tid >> 5;
    const int warpM = wid & 3, warpN = wid >> 2;
    const int b = blockIdx.y;
    const int px0 = blockIdx.x * 64;

    const int spx = tid & 63;
    const int rbase = (tid >> 6) * 8;
    const int shw = px0 + spx;
    const int sy = shw / WW, sx = shw - sy * WW;

    float c[2][4][4];
    #pragma unroll
    for (int mt = 0; mt < 2; mt++)
        #pragma unroll
        for (int nt = 0; nt < 4; nt++)
            #pragma unroll
            for (int r = 0; r < 4; r++) c[mt][nt][r] = 0.f;

    const int lmtx = lid >> 3, lrow = lid & 7;
    const int lk = ((lmtx & 1) << 3) + lrow;
    const int ln = warpN * 32 + ((lmtx >> 1) << 3);

    float v[16];
    auto stage_load = [&](int s) {
        #pragma unroll
        for (int sub = 0; sub < 2; sub++) {
            const int os = s * 2 + sub;
            float* vv = v + sub * 8;
            if (MODE <= 1) {
                constexpr int PER = CIN / 32;
                int tap = os / PER, ci0 = (os % PER) * 32;
                int dy = tap / 3 - 1, dx = tap % 3 - 1;
                int yy = sy + dy, xx = sx + dx;
                bool ok = ((unsigned)yy < HH) && ((unsigned)xx < WW);
                int off = yy * WW + xx;
                #pragma unroll
                for (int i = 0; i < 8; i++) {
                    int ci = ci0 + rbase + i;
                    const float* src;
                    if (MODE == 0)
                        src = (ci < 128) ? srcA + (size_t)(b*128+ci)*HWSZ
                                         : srcB + (size_t)(b*128+ci-128)*HWSZ;
                    else
                        src = srcA + (size_t)(b*128+ci)*HWSZ;
                    vv[i] = ok ? __ldg(src + off) : 0.f;
                }
            } else {
                int k = os >> 2, c0 = (os & 3) * 32;
                float oy = __ldg(g_off + (size_t)(b*18 + 2*k    )*HWSZ + shw);
                float ox = __ldg(g_off + (size_t)(b*18 + 2*k + 1)*HWSZ + shw);
                float py  = (float)(sy + k/3 - 1) + oy;
                float pxf = (float)(sx + k%3 - 1) + ox;
                float y0f = floorf(py), x0f = floorf(pxf);
                float wy1 = py - y0f, wy0 = 1.f - wy1;
                float wx1 = pxf - x0f, wx0 = 1.f - wx1;
                int y0 = (int)y0f, x0i = (int)x0f;
                int idx[4]; float wv[4];
                int ys[4] = {y0, y0, y0+1, y0+1};
                int xs[4] = {x0i, x0i+1, x0i, x0i+1};
                float ws[4] = {wy0*wx0, wy0*wx1, wy1*wx0, wy1*wx1};
                #pragma unroll
                for (int t = 0; t < 4; t++) {
                    bool va = (ys[t] >= 0) && (ys[t] <= HH-1) && (xs[t] >= 0) && (xs[t] <= WW-1);
                    int iy = min(max(ys[t], 0), HH-1);
                    int ix = min(max(xs[t], 0), WW-1);
                    idx[t] = iy*WW + ix;
                    wv[t]  = va ? ws[t] : 0.f;
                }
                #pragma unroll
                for (int i = 0; i < 8; i++) {
                    const float* xp = g_h1 + (size_t)(b*128 + c0 + rbase + i)*HWSZ;
                    vv[i] = wv[0]*__ldg(xp+idx[0]) + wv[1]*__ldg(xp+idx[1])
                          + wv[2]*__ldg(xp+idx[2]) + wv[3]*__ldg(xp+idx[3]);
                }
            }
        }
    };

    stage_load(0);

    for (int stage = 0; stage < NST; stage++) {
        const int buf = stage & 1;
        #pragma unroll
        for (int sub = 0; sub < 2; sub++)
            #pragma unroll
            for (int i = 0; i < 8; i++)
                sB[buf][sub*32 + rbase + i][spx] = f16_bits(v[sub*8 + i]);
        __syncthreads();
        if (stage + 1 < NST) stage_load(stage + 1);

        const uint32_t sbh = smem_u32(&sB[buf][0][0]);
        #pragma unroll
        for (int s = 0; s < 4; s++) {
            const int kk = stage * 4 + s;
            uint4 ah[2], al[2];
            #pragma unroll
            for (int mt = 0; mt < 2; mt++) {
                const uint4* ap = (const uint4*)Ag + (size_t)((kk * 8 + warpM * 2 + mt) * 2) * 32 + lid;
                ah[mt] = __ldg(ap);
                al[mt] = __ldg(ap + 32);
            }
            uint32_t bh[2][4];
            #pragma unroll
            for (int q = 0; q < 2; q++) {
                uint32_t off = (uint32_t)((s * 16 + lk) * 72 + ln + q * 16) * 2;
                asm volatile("ldmatrix.sync.aligned.m8n8.x4.trans.shared.b16 {%0,%1,%2,%3}, [%4];"
                    : "=r"(bh[q][0]), "=r"(bh[q][1]), "=r"(bh[q][2]), "=r"(bh[q][3]) : "r"(sbh + off));
            }
            #pragma unroll
            for (int mt = 0; mt < 2; mt++) {
                #pragma unroll
                for (int q = 0; q < 2; q++) {
                    #pragma unroll
                    for (int h = 0; h < 2; h++) {
                        float* cc = c[mt][q * 2 + h];
                        #define MMA(AF, B0, B1) \
                            asm volatile("mma.sync.aligned.m16n8k16.row.col.f32.f16.f16.f32 " \
                                "{%0,%1,%2,%3}, {%4,%5,%6,%7}, {%8,%9}, {%0,%1,%2,%3};" \
                                : "+f"(cc[0]), "+f"(cc[1]), "+f"(cc[2]), "+f"(cc[3]) \
                                : "r"(AF.x), "r"(AF.y), "r"(AF.z), "r"(AF.w), "r"(B0), "r"(B1))
                        MMA(ah[mt], bh[q][h * 2], bh[q][h * 2 + 1]);
                        MMA(al[mt], bh[q][h * 2], bh[q][h * 2 + 1]);
                        #undef MMA
                    }
                }
            }
        }
    }

    #pragma unroll
    for (int mt = 0; mt < 2; mt++) {
        int row = warpM * 32 + mt * 16 + (lid >> 2);
        float bi0 = bias[row], bi8 = bias[row + 8];
        float sa = 0.f, s2a = 0.f, sb = 0.f, s2b = 0.f;
        #pragma unroll
        for (int nt = 0; nt < 4; nt++) {
            int col = warpN * 32 + nt * 8 + (lid & 3) * 2;
            float v0 = c[mt][nt][0] + bi0, v1 = c[mt][nt][1] + bi0;
            float v2 = c[mt][nt][2] + bi8, v3 = c[mt][nt][3] + bi8;
            float* o0 = out + (size_t)(b * 128 + row) * HWSZ + px0 + col;
            *(float2*)o0 = make_float2(v0, v1);
            *(float2*)(o0 + 8 * HWSZ) = make_float2(v2, v3);
            if (BNS) {
                sa += v0 + v1; s2a += v0*v0 + v1*v1;
                sb += v2 + v3; s2b += v2*v2 + v3*v3;
            }
        }
        if (BNS) {
            #pragma unroll
            for (int o = 1; o < 4; o <<= 1) {
                sa  += __shfl_xor_sync(0xffffffffu, sa,  o);
                s2a += __shfl_xor_sync(0xffffffffu, s2a, o);
                sb  += __shfl_xor_sync(0xffffffffu, sb,  o);
                s2b += __shfl_xor_sync(0xffffffffu, s2b, o);
            }
            if ((lid & 3) == 0) {
                sSum[warpN][row][0] = sa;  sSum[warpN][row][1] = s2a;
                sSum[warpN][row + 8][0] = sb;  sSum[warpN][row + 8][1] = s2b;
            }
        }
    }
    if (BNS) {
        __syncthreads();
        if (tid < 128) {
            int bidx = blockIdx.y * 49 + blockIdx.x;
            g_bnp[(size_t)bidx * 256 + tid]       = sSum[0][tid][0] + sSum[1][tid][0];
            g_bnp[(size_t)bidx * 256 + 128 + tid] = sSum[0][tid][1] + sSum[1][tid][1];
        }
    }
}

// ---------------- merged weight prep ----------------
__global__ void prep_all_gemm(const float* __restrict__ w1, const float* __restrict__ w2,
                              const float* __restrict__ wd) {
    int which = blockIdx.y;
    int CIN = (which == 0) ? 256 : 128;
    const float* w = (which == 0) ? w1 : (which == 1) ? w2 : wd;
    uint8_t* dst = (which == 0) ? g_w1g : (which == 1) ? g_w2g : g_wdg;
    int K = CIN * 9;
    int i = blockIdx.x * 256 + threadIdx.x;
    if (i >= 128 * K) return;
    int co = i / K, kg = i % K;
    float v;
    if (which <= 1) { int tap = kg / CIN, ci = kg % CIN; v = w[((size_t)co * CIN + ci) * 9 + tap]; }
    else            { int k = kg >> 7,   c  = kg & 127;  v = w[((size_t)co * 128 + c) * 9 + k]; }
    uint16_t hb = f16_bits(v);
    uint16_t lb = f16_bits(v - f16_val(hb));
    int kk = kg >> 4, kin = kg & 15;
    int mt = co >> 4, row = co & 15;
    int lane = (row & 7) * 4 + ((kin & 7) >> 1);
    int reg = (row >> 3) + ((kin >> 3) << 1);
    int half = kin & 1;
    uint16_t* d16 = (uint16_t*)dst;
    size_t base = ((size_t)(kk * 8 + mt) * 2) * 128 + lane * 4 + reg;
    d16[base * 2 + half] = hb;
    d16[(base + 128) * 2 + half] = lb;
}

__global__ void prep_small(const float* __restrict__ wo, const float* __restrict__ wm) {
    int i = blockIdx.x*256 + threadIdx.x;
    if (i < CC*18) {
        int ci = i / 18, co = i % 18;
        #pragma unroll
        for (int k = 0; k < 9; k++) g_offwt[i*12+k] = wo[(co*CC+ci)*9+k];
        g_offwt[i*12+9]=0.f; g_offwt[i*12+10]=0.f; g_offwt[i*12+11]=0.f;
    }
    if (i < CC) {
        #pragma unroll
        for (int k = 0; k < 9; k++) g_maskwt[i*12+k] = wm[i*9+k];
        g_maskwt[i*12+9]=0.f; g_maskwt[i*12+10]=0.f; g_maskwt[i*12+11]=0.f;
    }
}

// ---------------- offset conv v2 ----------------
__global__ __launch_bounds__(112) void offconv_part()
{
    __shared__ float sw[16*18*12];
    const int tx = threadIdx.x;
    const int hy = threadIdx.y;
    const int tid = hy*14 + tx;
    const int h  = blockIdx.x*8 + hy;
    const int b  = blockIdx.y;
    const int ch = blockIdx.z;
    const int ci0 = ch*16;
    const int wb = tx*4;

    for (int i = tid; i < 16*18*3; i += 112)
        ((float4*)sw)[i] = __ldg(((const float4*)(g_offwt + (size_t)ci0*18*12)) + i);
    __syncthreads();

    float acc[18][4];
    #pragma unroll
    for (int co = 0; co < 18; co++)
        #pragma unroll
        for (int j = 0; j < 4; j++) acc[co][j] = 0.f;

    for (int ci = 0; ci < 16; ci++) {
        const float* ip = g_h1 + (size_t)(b*128 + ci0 + ci)*HWSZ;
        float r[3][6];
        #pragma unroll
        for (int dy = 0; dy < 3; dy++) {
            int yy = h + dy - 1;
            bool yok = ((unsigned)yy < HH);
            const float* rp = ip + yy*WW;
            #pragma unroll
            for (int dx = 0; dx < 6; dx++) {
                int xx = wb + dx - 1;
                r[dy][dx] = (yok && (unsigned)xx < WW) ? __ldg(rp + xx) : 0.f;
            }
        }
        const float4* wrow = (const float4*)(sw + ci*18*12);
        #pragma unroll
        for (int co = 0; co < 18; co++) {
            float4 wa  = wrow[co*3];
            float4 wb4 = wrow[co*3+1];
            float4 wc  = wrow[co*3+2];
            #pragma unroll
            for (int j = 0; j < 4; j++) {
                acc[co][j] += r[0][j]*wa.x + r[0][j+1]*wa.y + r[0][j+2]*wa.z
                            + r[1][j]*wa.w + r[1][j+1]*wb4.x + r[1][j+2]*wb4.y
                            + r[2][j]*wb4.z + r[2][j+1]*wb4.w + r[2][j+2]*wc.x;
            }
        }
    }
    #pragma unroll
    for (int co = 0; co < 18; co++) {
        float4* op = (float4*)(g_offp + (size_t)((ch*BN + b)*18 + co)*HWSZ + h*WW + wb);
        *op = make_float4(acc[co][0], acc[co][1], acc[co][2], acc[co][3]);
    }
}

__global__ __launch_bounds__(256) void offconv_reduce(const float* __restrict__ bias)
{
    int i = blockIdx.x*256 + threadIdx.x;                // float4 index
    if (i >= BN*18*HWSZ/4) return;
    int co = (i / (HWSZ/4)) % 18;
    float bi = bias[co];
    float4 v = make_float4(bi, bi, bi, bi);
    #pragma unroll
    for (int ch = 0; ch < 8; ch++) {
        float4 p = ((const float4*)g_offp)[(size_t)ch*(BN*18*HWSZ/4) + i];
        v.x += p.x; v.y += p.y; v.z += p.z; v.w += p.w;
    }
    ((float4*)g_off)[i] = v;
}

// ---------------- BN finalize (parallel two-half reduce) ----------------
__global__ void bn_finalize()
{
    __shared__ float ss[256], ss2[256];
    int t = threadIdx.x;
    int c = t & 127;
    int half = t >> 7;
    float s = 0.f, s2 = 0.f;
    for (int i = half; i < 392; i += 2) {
        s  += g_bnp[(size_t)i*256 + c];
        s2 += g_bnp[(size_t)i*256 + 128 + c];
    }
    ss[t] = s; ss2[t] = s2;
    __syncthreads();
    if (t < 128) {
        float st  = ss[t]  + ss[t + 128];
        float s2t = ss2[t] + ss2[t + 128];
        float n = (float)(BN*HWSZ);
        float mean = st / n;
        float var  = s2t / n - mean*mean;
        g_mean[t] = mean;
        g_rstd[t] = rsqrtf(var + 1e-5f);
    }
}

__global__ __launch_bounds__(256) void bngelu(
    const float* __restrict__ gamma, const float* __restrict__ beta,
    float* __restrict__ out)
{
    int i = blockIdx.x*256 + threadIdx.x;                // float4 index
    if (i >= BN*CC*HWSZ/4) return;
    int c = (i / (HWSZ/4)) & 127;
    float m = g_mean[c], rs = g_rstd[c], ga = gamma[c], be = beta[c];
    float4 v = ((const float4*)g_h3)[i];
    float4 o;
    float t;
    t = (v.x - m) * rs * ga + be;  o.x = 0.5f*t*(1.f + erff(t*0.70710678118654752440f));
    t = (v.y - m) * rs * ga + be;  o.y = 0.5f*t*(1.f + erff(t*0.70710678118654752440f));
    t = (v.z - m) * rs * ga + be;  o.z = 0.5f*t*(1.f + erff(t*0.70710678118654752440f));
    t = (v.w - m) * rs * ga + be;  o.w = 0.5f*t*(1.f + erff(t*0.70710678118654752440f));
    ((float4*)out)[i] = o;
}

// ---------------- mask conv v2 ----------------
__global__ __launch_bounds__(112) void maskconv_part(const float* __restrict__ hsrc)
{
    __shared__ float sw[32*12];
    const int tx = threadIdx.x;
    const int hy = threadIdx.y;
    const int tid = hy*14 + tx;
    const int h  = blockIdx.x*8 + hy;
    const int b  = blockIdx.y;
    const int ch = blockIdx.z;
    const int ci0 = ch*32;
    const int wb = tx*4;

    for (int i = tid; i < 32*3; i += 112)
        ((float4*)sw)[i] = __ldg(((const float4*)(g_maskwt + (size_t)ci0*12)) + i);
    __syncthreads();

    float acc[4] = {0.f, 0.f, 0.f, 0.f};
    for (int ci = 0; ci < 32; ci++) {
        const float* ip = hsrc + (size_t)(b*128 + ci0 + ci)*HWSZ;
        float r[3][6];
        #pragma unroll
        for (int dy = 0; dy < 3; dy++) {
            int yy = h + dy - 1;
            bool yok = ((unsigned)yy < HH);
            const float* rp = ip + yy*WW;
            #pragma unroll
            for (int dx = 0; dx < 6; dx++) {
                int xx = wb + dx - 1;
                r[dy][dx] = (yok && (unsigned)xx < WW) ? __ldg(rp + xx) : 0.f;
            }
        }
        const float4* wq = (const float4*)(sw + ci*12);
        float4 wa  = wq[0];
        float4 wb4 = wq[1];
        float4 wc  = wq[2];
        #pragma unroll
        for (int j = 0; j < 4; j++) {
            acc[j] += r[0][j]*wa.x + r[0][j+1]*wa.y + r[0][j+2]*wa.z
                    + r[1][j]*wa.w + r[1][j+1]*wb4.x + r[1][j+2]*wb4.y
                    + r[2][j]*wb4.z + r[2][j+1]*wb4.w + r[2][j+2]*wc.x;
        }
    }
    float4* op = (float4*)(g_maskp + (size_t)(ch*BN + b)*HWSZ + h*WW + wb);
    *op = make_float4(acc[0], acc[1], acc[2], acc[3]);
}

__global__ __launch_bounds__(256) void maskconv_reduce(
    const float* __restrict__ bias, float* __restrict__ out)
{
    int i = blockIdx.x*256 + threadIdx.x;                // float4 index
    if (i >= BN*HWSZ/4) return;
    float bi = bias[0];
    float4 v = make_float4(bi, bi, bi, bi);
    #pragma unroll
    for (int ch = 0; ch < 4; ch++) {
        float4 p = ((const float4*)g_maskp)[(size_t)ch*(BN*HWSZ/4) + i];
        v.x += p.x; v.y += p.y; v.z += p.z; v.w += p.w;
    }
    ((float4*)out)[i] = v;
}

// ---------------- launch ----------------
extern "C" void kernel_launch(void* const* d_in, const int* in_sizes, int n_in,
                              void* d_out, int out_size)
{
    const float* x       = (const float*)d_in[0];
    const float* y       = (const float*)d_in[1];
    const float* conv_w  = (const float*)d_in[2];
    const float* conv_b  = (const float*)d_in[3];
    const float* off_w   = (const float*)d_in[4];
    const float* off_b   = (const float*)d_in[5];
    const float* dcn_w   = (const float*)d_in[6];
    const float* dcn_b   = (const float*)d_in[7];
    const float* conv2_w = (const float*)d_in[8];
    const float* conv2_b = (const float*)d_in[9];
    const float* bn_g    = (const float*)d_in[10];
    const float* bn_b    = (const float*)d_in[11];
    const float* mask_w  = (const float*)d_in[12];
    const float* mask_b  = (const float*)d_in[13];
    float* out = (float*)d_out;

    float *p_h1, *p_h2, *p_h3;
    uint8_t *p_w1g, *p_w2g, *p_wdg;
    cudaGetSymbolAddress((void**)&p_h1,  g_h1);
    cudaGetSymbolAddress((void**)&p_h2,  g_h2);
    cudaGetSymbolAddress((void**)&p_h3,  g_h3);
    cudaGetSymbolAddress((void**)&p_w1g, g_w1g);
    cudaGetSymbolAddress((void**)&p_w2g, g_w2g);
    cudaGetSymbolAddress((void**)&p_wdg, g_wdg);

    // weight prep
    prep_all_gemm<<<dim3((128*2304 + 255)/256, 3), 256>>>(conv_w, conv2_w, dcn_w);
    prep_small<<<(CC*18 + 255)/256, 256>>>(off_w, mask_w);

    // conv1: fused im2col GEMM over concat(x,y)
    gemm_fused<256, 0, 0><<<dim3(49, BN), 256>>>(x, y, p_w1g, conv_b, p_h1);

    // offset conv 128 -> 18
    offconv_part<<<dim3(7, BN, 8), dim3(14, 8)>>>();
    offconv_reduce<<<(BN*18*HWSZ/4 + 255)/256, 256>>>(off_b);

    // dcn: fused bilinear-gather GEMM
    gemm_fused<128, 2, 0><<<dim3(49, BN), 256>>>(nullptr, nullptr, p_wdg, dcn_b, p_h2);

    // conv2: fused im2col GEMM + BN partial sums
    gemm_fused<128, 1, 1><<<dim3(49, BN), 256>>>(p_h2, nullptr, p_w2g, conv2_b, p_h3);

    // BN finalize + apply + GELU -> d_out
    bn_finalize<<<1, 256>>>();
    bngelu<<<(BN*CC*HWSZ/4 + 255)/256, 256>>>(bn_g, bn_b, out);

    // mask conv -> d_out tail
    maskconv_part<<<dim3(7, BN, 4), dim3(14, 8)>>>(out);
    maskconv_reduce<<<(BN*HWSZ/4 + 255)/256, 256>>>(mask_b, out + (size_t)BN*CC*HWSZ);

    (void)in_sizes; (void)n_in; (void)out_size;
}

// round 14
// speedup vs baseline: 1.0497x; 1.0497x over previous
#include <cuda_runtime.h>
#include <cuda_fp16.h>
#include <math.h>
#include <stdint.h>

#define BN 8
#define CC 128
#define HH 56
#define WW 56
#define HWSZ (HH*WW)

// ---------------- scratch ----------------
__device__ __align__(16) float g_h1[BN*CC*HWSZ];
__device__ __align__(16) float g_off[BN*18*HWSZ];
__device__ __align__(16) float g_offp[8*BN*18*HWSZ];
__device__ __align__(16) float g_h2[BN*CC*HWSZ];
__device__ __align__(16) float g_h3[BN*CC*HWSZ];
__device__ __align__(16) float g_maskp[4*BN*HWSZ];
__device__ __align__(16) float g_bnp[392*256];     // per-block BN partials [blk][s(128)|s2(128)]
__device__ float g_mean[CC];
__device__ float g_rstd[CC];
__device__ __align__(16) uint8_t g_w1g[144*8192];
__device__ __align__(16) uint8_t g_w2g[72*8192];
__device__ __align__(16) uint8_t g_wdg[72*8192];
__device__ __align__(16) float g_offwt[CC*18*12];
__device__ __align__(16) float g_maskwt[CC*12];

__device__ __forceinline__ uint32_t smem_u32(const void* p) {
    uint32_t a;
    asm("{ .reg .u64 t; cvta.to.shared.u64 t, %1; cvt.u32.u64 %0, t; }" : "=r"(a) : "l"(p));
    return a;
}
__device__ __forceinline__ uint16_t f16_bits(float x) {
    return __half_as_ushort(__float2half_rn(x));
}
__device__ __forceinline__ float f16_val(uint16_t u) {
    return __half2float(__ushort_as_half(u));
}

// ---------------- fused GEMM (fp16: A hi/lo pre-split, B single), K=32 per stage ----------------
// MODE 0: conv over concat(srcA,srcB)  (CIN=256)
// MODE 1: conv over srcA               (CIN=128)
// MODE 2: dcn - bilinear gather from g_h1 via g_off (CIN=128)
// BNS 1: emit per-block BN partial sums (conv2 only)
template<int CIN, int MODE, int BNS>
__global__ __launch_bounds__(256) void gemm_fused(
    const float* __restrict__ srcA, const float* __restrict__ srcB,
    const uint8_t* __restrict__ Ag,
    const float* __restrict__ bias, float* __restrict__ out)
{
    constexpr int NST = CIN * 9 / 32;
    __shared__ uint16_t sB[2][32][72];       // [buf][k][px]
    __shared__ float sSum[2][128][2];        // BN partials (BNS only)
    const int tid = threadIdx.x, lid = tid & 31, wid = tid >> 5;
    const int warpM = wid & 3, warpN = wid >> 2;
    const int b = blockIdx.y;
    const int px0 = blockIdx.x * 64;

    const int spx = tid & 63;
    const int rbase = (tid >> 6) * 8;
    const int shw = px0 + spx;
    const int sy = shw / WW, sx = shw - sy * WW;

    float c[2][4][4];
    #pragma unroll
    for (int mt = 0; mt < 2; mt++)
        #pragma unroll
        for (int nt = 0; nt < 4; nt++)
            #pragma unroll
            for (int r = 0; r < 4; r++) c[mt][nt][r] = 0.f;

    const int lmtx = lid >> 3, lrow = lid & 7;
    const int lk = ((lmtx & 1) << 3) + lrow;
    const int ln = warpN * 32 + ((lmtx >> 1) << 3);

    float v[8];
    auto stage_load = [&](int s) {
        if (MODE <= 1) {
            constexpr int PER = CIN / 32;
            int tap = s / PER, ci0 = (s % PER) * 32;
            int dy = tap / 3 - 1, dx = tap % 3 - 1;
            int yy = sy + dy, xx = sx + dx;
            bool ok = ((unsigned)yy < HH) && ((unsigned)xx < WW);
            int off = yy * WW + xx;
            #pragma unroll
            for (int i = 0; i < 8; i++) {
                int ci = ci0 + rbase + i;
                const float* src;
                if (MODE == 0)
                    src = (ci < 128) ? srcA + (size_t)(b*128+ci)*HWSZ
                                     : srcB + (size_t)(b*128+ci-128)*HWSZ;
                else
                    src = srcA + (size_t)(b*128+ci)*HWSZ;
                v[i] = ok ? __ldg(src + off) : 0.f;
            }
        } else {
            int k = s >> 2, c0 = (s & 3) * 32;
            float oy = __ldg(g_off + (size_t)(b*18 + 2*k    )*HWSZ + shw);
            float ox = __ldg(g_off + (size_t)(b*18 + 2*k + 1)*HWSZ + shw);
            float py  = (float)(sy + k/3 - 1) + oy;
            float pxf = (float)(sx + k%3 - 1) + ox;
            float y0f = floorf(py), x0f = floorf(pxf);
            float wy1 = py - y0f, wy0 = 1.f - wy1;
            float wx1 = pxf - x0f, wx0 = 1.f - wx1;
            int y0 = (int)y0f, x0i = (int)x0f;
            int idx[4]; float wv[4];
            int ys[4] = {y0, y0, y0+1, y0+1};
            int xs[4] = {x0i, x0i+1, x0i, x0i+1};
            float ws[4] = {wy0*wx0, wy0*wx1, wy1*wx0, wy1*wx1};
            #pragma unroll
            for (int t = 0; t < 4; t++) {
                bool va = (ys[t] >= 0) && (ys[t] <= HH-1) && (xs[t] >= 0) && (xs[t] <= WW-1);
                int iy = min(max(ys[t], 0), HH-1);
                int ix = min(max(xs[t], 0), WW-1);
                idx[t] = iy*WW + ix;
                wv[t]  = va ? ws[t] : 0.f;
            }
            #pragma unroll
            for (int i = 0; i < 8; i++) {
                const float* xp = g_h1 + (size_t)(b*128 + c0 + rbase + i)*HWSZ;
                v[i] = wv[0]*__ldg(xp+idx[0]) + wv[1]*__ldg(xp+idx[1])
                     + wv[2]*__ldg(xp+idx[2]) + wv[3]*__ldg(xp+idx[3]);
            }
        }
    };

    stage_load(0);

    for (int stage = 0; stage < NST; stage++) {
        const int buf = stage & 1;
        #pragma unroll
        for (int i = 0; i < 8; i++)
            sB[buf][rbase + i][spx] = f16_bits(v[i]);
        __syncthreads();
        if (stage + 1 < NST) stage_load(stage + 1);

        const uint32_t sbh = smem_u32(&sB[buf][0][0]);
        #pragma unroll
        for (int s = 0; s < 2; s++) {
            const int kk = stage * 2 + s;
            uint4 ah[2], al[2];
            #pragma unroll
            for (int mt = 0; mt < 2; mt++) {
                const uint4* ap = (const uint4*)Ag + (size_t)((kk * 8 + warpM * 2 + mt) * 2) * 32 + lid;
                ah[mt] = __ldg(ap);
                al[mt] = __ldg(ap + 32);
            }
            uint32_t bh[2][4];
            #pragma unroll
            for (int q = 0; q < 2; q++) {
                uint32_t off = (uint32_t)((s * 16 + lk) * 72 + ln + q * 16) * 2;
                asm volatile("ldmatrix.sync.aligned.m8n8.x4.trans.shared.b16 {%0,%1,%2,%3}, [%4];"
                    : "=r"(bh[q][0]), "=r"(bh[q][1]), "=r"(bh[q][2]), "=r"(bh[q][3]) : "r"(sbh + off));
            }
            #pragma unroll
            for (int mt = 0; mt < 2; mt++) {
                #pragma unroll
                for (int q = 0; q < 2; q++) {
                    #pragma unroll
                    for (int h = 0; h < 2; h++) {
                        float* cc = c[mt][q * 2 + h];
                        #define MMA(AF, B0, B1) \
                            asm volatile("mma.sync.aligned.m16n8k16.row.col.f32.f16.f16.f32 " \
                                "{%0,%1,%2,%3}, {%4,%5,%6,%7}, {%8,%9}, {%0,%1,%2,%3};" \
                                : "+f"(cc[0]), "+f"(cc[1]), "+f"(cc[2]), "+f"(cc[3]) \
                                : "r"(AF.x), "r"(AF.y), "r"(AF.z), "r"(AF.w), "r"(B0), "r"(B1))
                        MMA(ah[mt], bh[q][h * 2], bh[q][h * 2 + 1]);
                        MMA(al[mt], bh[q][h * 2], bh[q][h * 2 + 1]);
                        #undef MMA
                    }
                }
            }
        }
    }

    #pragma unroll
    for (int mt = 0; mt < 2; mt++) {
        int row = warpM * 32 + mt * 16 + (lid >> 2);
        float bi0 = bias[row], bi8 = bias[row + 8];
        float sa = 0.f, s2a = 0.f, sb = 0.f, s2b = 0.f;
        #pragma unroll
        for (int nt = 0; nt < 4; nt++) {
            int col = warpN * 32 + nt * 8 + (lid & 3) * 2;
            float v0 = c[mt][nt][0] + bi0, v1 = c[mt][nt][1] + bi0;
            float v2 = c[mt][nt][2] + bi8, v3 = c[mt][nt][3] + bi8;
            float* o0 = out + (size_t)(b * 128 + row) * HWSZ + px0 + col;
            *(float2*)o0 = make_float2(v0, v1);
            *(float2*)(o0 + 8 * HWSZ) = make_float2(v2, v3);
            if (BNS) {
                sa += v0 + v1; s2a += v0*v0 + v1*v1;
                sb += v2 + v3; s2b += v2*v2 + v3*v3;
            }
        }
        if (BNS) {
            #pragma unroll
            for (int o = 1; o < 4; o <<= 1) {
                sa  += __shfl_xor_sync(0xffffffffu, sa,  o);
                s2a += __shfl_xor_sync(0xffffffffu, s2a, o);
                sb  += __shfl_xor_sync(0xffffffffu, sb,  o);
                s2b += __shfl_xor_sync(0xffffffffu, s2b, o);
            }
            if ((lid & 3) == 0) {
                sSum[warpN][row][0] = sa;  sSum[warpN][row][1] = s2a;
                sSum[warpN][row + 8][0] = sb;  sSum[warpN][row + 8][1] = s2b;
            }
        }
    }
    if (BNS) {
        __syncthreads();
        if (tid < 128) {
            int bidx = blockIdx.y * 49 + blockIdx.x;
            g_bnp[(size_t)bidx * 256 + tid]       = sSum[0][tid][0] + sSum[1][tid][0];
            g_bnp[(size_t)bidx * 256 + 128 + tid] = sSum[0][tid][1] + sSum[1][tid][1];
        }
    }
}

// ---------------- merged weight prep ----------------
__global__ void prep_all_gemm(const float* __restrict__ w1, const float* __restrict__ w2,
                              const float* __restrict__ wd) {
    int which = blockIdx.y;
    int CIN = (which == 0) ? 256 : 128;
    const float* w = (which == 0) ? w1 : (which == 1) ? w2 : wd;
    uint8_t* dst = (which == 0) ? g_w1g : (which == 1) ? g_w2g : g_wdg;
    int K = CIN * 9;
    int i = blockIdx.x * 256 + threadIdx.x;
    if (i >= 128 * K) return;
    int co = i / K, kg = i % K;
    float v;
    if (which <= 1) { int tap = kg / CIN, ci = kg % CIN; v = w[((size_t)co * CIN + ci) * 9 + tap]; }
    else            { int k = kg >> 7,   c  = kg & 127;  v = w[((size_t)co * 128 + c) * 9 + k]; }
    uint16_t hb = f16_bits(v);
    uint16_t lb = f16_bits(v - f16_val(hb));
    int kk = kg >> 4, kin = kg & 15;
    int mt = co >> 4, row = co & 15;
    int lane = (row & 7) * 4 + ((kin & 7) >> 1);
    int reg = (row >> 3) + ((kin >> 3) << 1);
    int half = kin & 1;
    uint16_t* d16 = (uint16_t*)dst;
    size_t base = ((size_t)(kk * 8 + mt) * 2) * 128 + lane * 4 + reg;
    d16[base * 2 + half] = hb;
    d16[(base + 128) * 2 + half] = lb;
}

__global__ void prep_small(const float* __restrict__ wo, const float* __restrict__ wm) {
    int i = blockIdx.x*256 + threadIdx.x;
    if (i < CC*18) {
        int ci = i / 18, co = i % 18;
        #pragma unroll
        for (int k = 0; k < 9; k++) g_offwt[i*12+k] = wo[(co*CC+ci)*9+k];
        g_offwt[i*12+9]=0.f; g_offwt[i*12+10]=0.f; g_offwt[i*12+11]=0.f;
    }
    if (i < CC) {
        #pragma unroll
        for (int k = 0; k < 9; k++) g_maskwt[i*12+k] = wm[i*9+k];
        g_maskwt[i*12+9]=0.f; g_maskwt[i*12+10]=0.f; g_maskwt[i*12+11]=0.f;
    }
}

// ---------------- offset conv v3: co split in halves (9 co/block), smem weights ----------------
__global__ __launch_bounds__(112) void offconv_part()
{
    __shared__ float sw[16*9*12];            // 6912 B
    const int tx = threadIdx.x;              // 0..13 -> w groups of 4
    const int hy = threadIdx.y;              // 0..7
    const int tid = hy*14 + tx;
    const int h  = blockIdx.x*8 + hy;
    const int b  = blockIdx.y;
    const int ch = blockIdx.z >> 1;          // ci chunk 0..7
    const int coh = blockIdx.z & 1;          // co half 0..1
    const int ci0 = ch*16;
    const int co0 = coh*9;
    const int wb = tx*4;

    // load weights for 16 ci x 9 co (non-contiguous co slice)
    for (int i = tid; i < 16*9*3; i += 112) {
        int ci = i / 27;
        int j  = i % 27;
        int co = j / 3;
        int q  = j % 3;
        ((float4*)sw)[i] = __ldg((const float4*)(g_offwt) +
                                 ((size_t)(ci0+ci)*18 + co0 + co)*3 + q);
    }
    __syncthreads();

    float acc[9][4];
    #pragma unroll
    for (int co = 0; co < 9; co++)
        #pragma unroll
        for (int j = 0; j < 4; j++) acc[co][j] = 0.f;

    for (int ci = 0; ci < 16; ci++) {
        const float* ip = g_h1 + (size_t)(b*128 + ci0 + ci)*HWSZ;
        float r[3][6];
        #pragma unroll
        for (int dy = 0; dy < 3; dy++) {
            int yy = h + dy - 1;
            bool yok = ((unsigned)yy < HH);
            const float* rp = ip + yy*WW;
            #pragma unroll
            for (int dx = 0; dx < 6; dx++) {
                int xx = wb + dx - 1;
                r[dy][dx] = (yok && (unsigned)xx < WW) ? __ldg(rp + xx) : 0.f;
            }
        }
        const float4* wrow = (const float4*)(sw + ci*9*12);
        #pragma unroll
        for (int co = 0; co < 9; co++) {
            float4 wa  = wrow[co*3];
            float4 wb4 = wrow[co*3+1];
            float4 wc  = wrow[co*3+2];
            #pragma unroll
            for (int j = 0; j < 4; j++) {
                acc[co][j] += r[0][j]*wa.x + r[0][j+1]*wa.y + r[0][j+2]*wa.z
                            + r[1][j]*wa.w + r[1][j+1]*wb4.x + r[1][j+2]*wb4.y
                            + r[2][j]*wb4.z + r[2][j+1]*wb4.w + r[2][j+2]*wc.x;
            }
        }
    }
    #pragma unroll
    for (int co = 0; co < 9; co++) {
        float4* op = (float4*)(g_offp + (size_t)((ch*BN + b)*18 + co0 + co)*HWSZ + h*WW + wb);
        *op = make_float4(acc[co][0], acc[co][1], acc[co][2], acc[co][3]);
    }
}

__global__ __launch_bounds__(256) void offconv_reduce(const float* __restrict__ bias)
{
    int i = blockIdx.x*256 + threadIdx.x;                // float4 index
    if (i >= BN*18*HWSZ/4) return;
    int co = (i / (HWSZ/4)) % 18;
    float bi = bias[co];
    float4 v = make_float4(bi, bi, bi, bi);
    #pragma unroll
    for (int ch = 0; ch < 8; ch++) {
        float4 p = ((const float4*)g_offp)[(size_t)ch*(BN*18*HWSZ/4) + i];
        v.x += p.x; v.y += p.y; v.z += p.z; v.w += p.w;
    }
    ((float4*)g_off)[i] = v;
}

// ---------------- BN finalize (parallel two-half reduce) ----------------
__global__ void bn_finalize()
{
    __shared__ float ss[256], ss2[256];
    int t = threadIdx.x;
    int c = t & 127;
    int half = t >> 7;
    float s = 0.f, s2 = 0.f;
    for (int i = half; i < 392; i += 2) {
        s  += g_bnp[(size_t)i*256 + c];
        s2 += g_bnp[(size_t)i*256 + 128 + c];
    }
    ss[t] = s; ss2[t] = s2;
    __syncthreads();
    if (t < 128) {
        float st  = ss[t]  + ss[t + 128];
        float s2t = ss2[t] + ss2[t + 128];
        float n = (float)(BN*HWSZ);
        float mean = st / n;
        float var  = s2t / n - mean*mean;
        g_mean[t] = mean;
        g_rstd[t] = rsqrtf(var + 1e-5f);
    }
}

__global__ __launch_bounds__(256) void bngelu(
    const float* __restrict__ gamma, const float* __restrict__ beta,
    float* __restrict__ out)
{
    int i = blockIdx.x*256 + threadIdx.x;                // float4 index
    if (i >= BN*CC*HWSZ/4) return;
    int c = (i / (HWSZ/4)) & 127;
    float m = g_mean[c], rs = g_rstd[c], ga = gamma[c], be = beta[c];
    float4 v = ((const float4*)g_h3)[i];
    float4 o;
    float t;
    t = (v.x - m) * rs * ga + be;  o.x = 0.5f*t*(1.f + erff(t*0.70710678118654752440f));
    t = (v.y - m) * rs * ga + be;  o.y = 0.5f*t*(1.f + erff(t*0.70710678118654752440f));
    t = (v.z - m) * rs * ga + be;  o.z = 0.5f*t*(1.f + erff(t*0.70710678118654752440f));
    t = (v.w - m) * rs * ga + be;  o.w = 0.5f*t*(1.f + erff(t*0.70710678118654752440f));
    ((float4*)out)[i] = o;
}

// ---------------- mask conv v2 ----------------
__global__ __launch_bounds__(112) void maskconv_part(const float* __restrict__ hsrc)
{
    __shared__ float sw[32*12];
    const int tx = threadIdx.x;
    const int hy = threadIdx.y;
    const int tid = hy*14 + tx;
    const int h  = blockIdx.x*8 + hy;
    const int b  = blockIdx.y;
    const int ch = blockIdx.z;
    const int ci0 = ch*32;
    const int wb = tx*4;

    for (int i = tid; i < 32*3; i += 112)
        ((float4*)sw)[i] = __ldg(((const float4*)(g_maskwt + (size_t)ci0*12)) + i);
    __syncthreads();

    float acc[4] = {0.f, 0.f, 0.f, 0.f};
    for (int ci = 0; ci < 32; ci++) {
        const float* ip = hsrc + (size_t)(b*128 + ci0 + ci)*HWSZ;
        float r[3][6];
        #pragma unroll
        for (int dy = 0; dy < 3; dy++) {
            int yy = h + dy - 1;
            bool yok = ((unsigned)yy < HH);
            const float* rp = ip + yy*WW;
            #pragma unroll
            for (int dx = 0; dx < 6; dx++) {
                int xx = wb + dx - 1;
                r[dy][dx] = (yok && (unsigned)xx < WW) ? __ldg(rp + xx) : 0.f;
            }
        }
        const float4* wq = (const float4*)(sw + ci*12);
        float4 wa  = wq[0];
        float4 wb4 = wq[1];
        float4 wc  = wq[2];
        #pragma unroll
        for (int j = 0; j < 4; j++) {
            acc[j] += r[0][j]*wa.x + r[0][j+1]*wa.y + r[0][j+2]*wa.z
                    + r[1][j]*wa.w + r[1][j+1]*wb4.x + r[1][j+2]*wb4.y
                    + r[2][j]*wb4.z + r[2][j+1]*wb4.w + r[2][j+2]*wc.x;
        }
    }
    float4* op = (float4*)(g_maskp + (size_t)(ch*BN + b)*HWSZ + h*WW + wb);
    *op = make_float4(acc[0], acc[1], acc[2], acc[3]);
}

__global__ __launch_bounds__(256) void maskconv_reduce(
    const float* __restrict__ bias, float* __restrict__ out)
{
    int i = blockIdx.x*256 + threadIdx.x;                // float4 index
    if (i >= BN*HWSZ/4) return;
    float bi = bias[0];
    float4 v = make_float4(bi, bi, bi, bi);
    #pragma unroll
    for (int ch = 0; ch < 4; ch++) {
        float4 p = ((const float4*)g_maskp)[(size_t)ch*(BN*HWSZ/4) + i];
        v.x += p.x; v.y += p.y; v.z += p.z; v.w += p.w;
    }
    ((float4*)out)[i] = v;
}

// ---------------- launch ----------------
extern "C" void kernel_launch(void* const* d_in, const int* in_sizes, int n_in,
                              void* d_out, int out_size)
{
    const float* x       = (const float*)d_in[0];
    const float* y       = (const float*)d_in[1];
    const float* conv_w  = (const float*)d_in[2];
    const float* conv_b  = (const float*)d_in[3];
    const float* off_w   = (const float*)d_in[4];
    const float* off_b   = (const float*)d_in[5];
    const float* dcn_w   = (const float*)d_in[6];
    const float* dcn_b   = (const float*)d_in[7];
    const float* conv2_w = (const float*)d_in[8];
    const float* conv2_b = (const float*)d_in[9];
    const float* bn_g    = (const float*)d_in[10];
    const float* bn_b    = (const float*)d_in[11];
    const float* mask_w  = (const float*)d_in[12];
    const float* mask_b  = (const float*)d_in[13];
    float* out = (float*)d_out;

    float *p_h1, *p_h2, *p_h3;
    uint8_t *p_w1g, *p_w2g, *p_wdg;
    cudaGetSymbolAddress((void**)&p_h1,  g_h1);
    cudaGetSymbolAddress((void**)&p_h2,  g_h2);
    cudaGetSymbolAddress((void**)&p_h3,  g_h3);
    cudaGetSymbolAddress((void**)&p_w1g, g_w1g);
    cudaGetSymbolAddress((void**)&p_w2g, g_w2g);
    cudaGetSymbolAddress((void**)&p_wdg, g_wdg);

    // weight prep
    prep_all_gemm<<<dim3((128*2304 + 255)/256, 3), 256>>>(conv_w, conv2_w, dcn_w);
    prep_small<<<(CC*18 + 255)/256, 256>>>(off_w, mask_w);

    // conv1: fused im2col GEMM over concat(x,y)
    gemm_fused<256, 0, 0><<<dim3(49, BN), 256>>>(x, y, p_w1g, conv_b, p_h1);

    // offset conv 128 -> 18 (8 ci-chunks x 2 co-halves)
    offconv_part<<<dim3(7, BN, 16), dim3(14, 8)>>>();
    offconv_reduce<<<(BN*18*HWSZ/4 + 255)/256, 256>>>(off_b);

    // dcn: fused bilinear-gather GEMM
    gemm_fused<128, 2, 0><<<dim3(49, BN), 256>>>(nullptr, nullptr, p_wdg, dcn_b, p_h2);

    // conv2: fused im2col GEMM + BN partial sums
    gemm_fused<128, 1, 1><<<dim3(49, BN), 256>>>(p_h2, nullptr, p_w2g, conv2_b, p_h3);

    // BN finalize + apply + GELU -> d_out
    bn_finalize<<<1, 256>>>();
    bngelu<<<(BN*CC*HWSZ/4 + 255)/256, 256>>>(bn_g, bn_b, out);

    // mask conv -> d_out tail
    maskconv_part<<<dim3(7, BN, 4), dim3(14, 8)>>>(out);
    maskconv_reduce<<<(BN*HWSZ/4 + 255)/256, 256>>>(mask_b, out + (size_t)BN*CC*HWSZ);

    (void)in_sizes; (void)n_in; (void)out_size;
}